// round 10
// baseline (speedup 1.0000x reference)
#include <cuda_runtime.h>
#include <cstddef>
#include <cstdint>

#define Bz 32
#define Tt 4096
#define Uu 512

// 256MB scratch: holds XW = x@w_x + b_h, overwritten in place by H during scan.
__device__ float g_xw[(size_t)Bz * Tt * Uu];
// per-group monotonic counters (8 groups, 128B apart)
__device__ unsigned int g_ctr[8 * 32];

// ---------------------------------------------------------------------------
__device__ __forceinline__ float my_tanh(float x) {
    float ax = fabsf(x);
    if (ax < 0.125f) {
        float x2 = x * x;
        return x * (1.f + x2 * (-0.333333333f + x2 * 0.133333333f));
    }
    float e = __expf(2.f * ax);
    float r = 1.f - 2.f / (1.f + e);
    return copysignf(r, x);
}

// ---------------------------------------------------------------------------
// SGEMM with bias: C[M,512] = A[M,512] @ B[512,512] + bias[512]
// (phase 1 only now). Optional counter reset rides along.
// ---------------------------------------------------------------------------
__global__ __launch_bounds__(256) void sgemm_bias(
    const float* __restrict__ A, const float* __restrict__ Bm,
    const float* __restrict__ bias, float* __restrict__ C,
    unsigned int* __restrict__ rctr)
{
    __shared__ float As[16][132];
    __shared__ float Bs[16][128];
    const int tid = threadIdx.x;
    const int tx = tid & 15, ty = tid >> 4;
    const size_t row0 = (size_t)blockIdx.y * 128;
    const int col0 = blockIdx.x * 128;

    if (rctr && blockIdx.x == 0 && blockIdx.y == 0 && tid < 8)
        rctr[tid * 32] = 0u;

    float acc[8][8];
#pragma unroll
    for (int i = 0; i < 8; i++)
#pragma unroll
        for (int j = 0; j < 8; j++) acc[i][j] = 0.f;

    for (int k0 = 0; k0 < 512; k0 += 16) {
#pragma unroll
        for (int l = 0; l < 2; l++) {
            int f = tid + l * 256;
            int ar = f >> 2, ak = (f & 3) << 2;
            float4 av = *(const float4*)&A[(row0 + ar) * 512 + k0 + ak];
            As[ak + 0][ar] = av.x;
            As[ak + 1][ar] = av.y;
            As[ak + 2][ar] = av.z;
            As[ak + 3][ar] = av.w;
            int br = f >> 5, bc = (f & 31) << 2;
            *(float4*)&Bs[br][bc] =
                *(const float4*)&Bm[(size_t)(k0 + br) * 512 + col0 + bc];
        }
        __syncthreads();
#pragma unroll
        for (int k = 0; k < 16; k++) {
            float a[8], b[8];
            *(float4*)&a[0] = *(const float4*)&As[k][ty * 8];
            *(float4*)&a[4] = *(const float4*)&As[k][ty * 8 + 4];
            *(float4*)&b[0] = *(const float4*)&Bs[k][tx * 8];
            *(float4*)&b[4] = *(const float4*)&Bs[k][tx * 8 + 4];
#pragma unroll
            for (int i = 0; i < 8; i++)
#pragma unroll
                for (int j = 0; j < 8; j++)
                    acc[i][j] = fmaf(a[i], b[j], acc[i][j]);
        }
        __syncthreads();
    }

    float bj[8];
    *(float4*)&bj[0] = *(const float4*)&bias[col0 + tx * 8];
    *(float4*)&bj[4] = *(const float4*)&bias[col0 + tx * 8 + 4];
#pragma unroll
    for (int i = 0; i < 8; i++) {
        size_t r = row0 + ty * 8 + i;
        float4 v0 = make_float4(acc[i][0] + bj[0], acc[i][1] + bj[1],
                                acc[i][2] + bj[2], acc[i][3] + bj[3]);
        float4 v1 = make_float4(acc[i][4] + bj[4], acc[i][5] + bj[5],
                                acc[i][6] + bj[6], acc[i][7] + bj[7]);
        *(float4*)&C[r * 512 + col0 + tx * 8] = v0;
        *(float4*)&C[r * 512 + col0 + tx * 8 + 4] = v1;
    }
}

// ---------------------------------------------------------------------------
// Recurrent scan v8 = v7's proven h-path, verbatim, + Y fused into the
// barrier bubble. During the fence+atomic+spin (warp 7 lane 0), warps 0-3
// compute y_{t-1} = h_{t-1} @ w_y + b_y from h_s (which still holds h_{t-1})
// using a bank-staggered w_y slice in SMEM. Phase-3 GEMM is eliminated.
// ---------------------------------------------------------------------------
__global__ __launch_bounds__(256, 1) void rnn_scan8(
    const float* __restrict__ w_h, const float* __restrict__ w_y,
    const float* __restrict__ b_y, const float* __restrict__ h0,
    float* __restrict__ out)
{
    extern __shared__ float smem[];
    float* w_s  = smem;                     // 512*32 = 16384 floats
    float* h_s  = smem + 16384;             // 4*512  = 2048 floats
    float* psum = smem + 16384 + 2048;      // 8*128  = 1024 floats
    float* wy_s = smem + 16384 + 2048 + 1024;  // 128 rows * 132 = 16896 floats

    const int tid = threadIdx.x;
    const int grp = blockIdx.x >> 4;     // 0..7
    const int cig = blockIdx.x & 15;     // 0..15
    const int b0 = grp << 2;
    const int u0 = cig << 5;

    // ---- load w_h slice: w_s[d*32 + j] = w_h[d*512 + u0 + j] ----
    for (int i = tid; i < 16384; i += 256) {
        int d = i >> 5, j = i & 31;
        w_s[i] = w_h[d * 512 + u0 + j];
    }
    // ---- load w_y slice, transposed + bank-staggered:
    //      wy_s[(j*4 + (d>>7))*132 + (d&127)] = w_y[d*512 + u0 + j]
    for (int i = tid; i < 16384; i += 256) {
        int d = i >> 5, j = i & 31;
        wy_s[(j * 4 + (d >> 7)) * 132 + (d & 127)] = w_y[d * 512 + u0 + j];
    }

    const int ut   = tid & 7;
    const int dcw  = tid >> 3;
    const int lane = tid & 31;
    const int warp = tid >> 5;
    const int d0q  = dcw << 2;
    const float4* w_s4 = (const float4*)w_s;   // [d*8 + ut]
    const float4* h_s4 = (const float4*)h_s;   // [b*128 + d4]
    unsigned int* ctr = &g_ctr[grp * 32];

    // writer threads (tid < 128): own h-output slot + xw register prefetch
    size_t oidx = 0;
    float xw_pf = 0.f;
    if (tid < 128) {
        int ul = tid >> 2, bq = tid & 3;
        oidx = ((size_t)(b0 + bq) * Tt) * Uu + u0 + ul;
        xw_pf = g_xw[oidx];              // xw for t = 0
    }
    // y threads (tid < 128): uy = tid>>2, q = tid&3; bias in register
    const int uy = tid >> 2;
    const int qq = tid & 3;
    float by = (tid < 128) ? b_y[u0 + uy] : 0.f;
    const float4* wyr = (const float4*)&wy_s[tid * 132];   // row tid = uy*4+q

    __syncthreads();

    for (int t = 0; t < Tt; t++) {
        // ---- load h_{t-1} into SMEM (4 batches x 512) ----
        if (t == 0) {
            for (int i = tid; i < 2048; i += 256) h_s[i] = h0[i & 511];
        } else {
            for (int i = tid; i < 512; i += 256) {
                int b = i >> 7, d4 = i & 127;
                ((float4*)h_s)[i] =
                    *((const float4*)&g_xw[((size_t)(b0 + b) * Tt + (t - 1)) * Uu] + d4);
            }
        }
        __syncthreads();

        // ---- h partial dot products: 4 units x 4 batches over 16 d ----
        float acc[16];
#pragma unroll
        for (int z = 0; z < 16; z++) acc[z] = 0.f;
#pragma unroll
        for (int i = 0; i < 4; i++) {
            float4 hv[4];
            hv[0] = h_s4[d0q + i];
            hv[1] = h_s4[128 + d0q + i];
            hv[2] = h_s4[256 + d0q + i];
            hv[3] = h_s4[384 + d0q + i];
#pragma unroll
            for (int j = 0; j < 4; j++) {
                float4 wv = w_s4[((d0q + i) * 4 + j) * 8 + ut];
                const float w0 = wv.x, w1 = wv.y, w2 = wv.z, w3 = wv.w;
#pragma unroll
                for (int b = 0; b < 4; b++) {
                    float hb = ((const float*)&hv[b])[j];
                    acc[b * 4 + 0] = fmaf(w0, hb, acc[b * 4 + 0]);
                    acc[b * 4 + 1] = fmaf(w1, hb, acc[b * 4 + 1]);
                    acc[b * 4 + 2] = fmaf(w2, hb, acc[b * 4 + 2]);
                    acc[b * 4 + 3] = fmaf(w3, hb, acc[b * 4 + 3]);
                }
            }
        }

        // ---- warp reduce over the 4 d-chunks (lane bits 3,4) ----
#pragma unroll
        for (int z = 0; z < 16; z++) {
            acc[z] += __shfl_xor_sync(0xffffffffu, acc[z], 8);
            acc[z] += __shfl_xor_sync(0xffffffffu, acc[z], 16);
        }
        if (lane < 8) {
#pragma unroll
            for (int uj = 0; uj < 4; uj++)
#pragma unroll
                for (int b = 0; b < 4; b++)
                    psum[warp * 128 + ((ut * 4 + uj) << 2) + b] = acc[b * 4 + uj];
        }
        __syncthreads();

        // ---- final reduce over 8 warps, tanh, write h_t in place over xw ----
        if (tid < 128) {
            float s = 0.f;
#pragma unroll
            for (int w = 0; w < 8; w++) s += psum[w * 128 + tid];
            float val = my_tanh(s + xw_pf);
            g_xw[oidx + (size_t)t * Uu] = val;
            if (t + 1 < Tt)   // prefetch next xw; latency hides under barrier
                xw_pf = g_xw[oidx + (size_t)(t + 1) * Uu];
        }
        __syncthreads();   // all h stores of this CTA issued

        // ---- barrier spin (warp 7 lane 0)  ∥  y_{t-1} on warps 0-3 ----
        if (tid == 224) {
            __threadfence();
            atomicAdd(ctr, 1u);
            unsigned int target = (unsigned int)(16 * (t + 1));
            unsigned int v;
            do {
                asm volatile("ld.global.acquire.gpu.u32 %0, [%1];"
                             : "=r"(v) : "l"(ctr));
            } while (v < target);
        }
        if (t > 0 && tid < 128) {
            // y_{t-1}[b][u0+uy] over d; this thread: quarter qq (128 d)
            float4 a0 = make_float4(0.f, 0.f, 0.f, 0.f);
            float4 a1 = a0, a2 = a0, a3 = a0;
#pragma unroll
            for (int dd = 0; dd < 32; dd++) {
                float4 wv = wyr[dd];
                float4 h0v = h_s4[0 * 128 + qq * 32 + dd];
                float4 h1v = h_s4[1 * 128 + qq * 32 + dd];
                float4 h2v = h_s4[2 * 128 + qq * 32 + dd];
                float4 h3v = h_s4[3 * 128 + qq * 32 + dd];
                a0.x = fmaf(wv.x, h0v.x, a0.x); a0.y = fmaf(wv.y, h0v.y, a0.y);
                a0.z = fmaf(wv.z, h0v.z, a0.z); a0.w = fmaf(wv.w, h0v.w, a0.w);
                a1.x = fmaf(wv.x, h1v.x, a1.x); a1.y = fmaf(wv.y, h1v.y, a1.y);
                a1.z = fmaf(wv.z, h1v.z, a1.z); a1.w = fmaf(wv.w, h1v.w, a1.w);
                a2.x = fmaf(wv.x, h2v.x, a2.x); a2.y = fmaf(wv.y, h2v.y, a2.y);
                a2.z = fmaf(wv.z, h2v.z, a2.z); a2.w = fmaf(wv.w, h2v.w, a2.w);
                a3.x = fmaf(wv.x, h3v.x, a3.x); a3.y = fmaf(wv.y, h3v.y, a3.y);
                a3.z = fmaf(wv.z, h3v.z, a3.z); a3.w = fmaf(wv.w, h3v.w, a3.w);
            }
            float s0 = (a0.x + a0.y) + (a0.z + a0.w);
            float s1 = (a1.x + a1.y) + (a1.z + a1.w);
            float s2 = (a2.x + a2.y) + (a2.z + a2.w);
            float s3 = (a3.x + a3.y) + (a3.z + a3.w);
            // reduce over qq (lane bits 0,1)
            s0 += __shfl_xor_sync(0xffffffffu, s0, 1);
            s0 += __shfl_xor_sync(0xffffffffu, s0, 2);
            s1 += __shfl_xor_sync(0xffffffffu, s1, 1);
            s1 += __shfl_xor_sync(0xffffffffu, s1, 2);
            s2 += __shfl_xor_sync(0xffffffffu, s2, 1);
            s2 += __shfl_xor_sync(0xffffffffu, s2, 2);
            s3 += __shfl_xor_sync(0xffffffffu, s3, 1);
            s3 += __shfl_xor_sync(0xffffffffu, s3, 2);
            if (qq == 0) {
                size_t yb = (size_t)(t - 1) * Uu + u0 + uy;
                out[(size_t)(b0 + 0) * Tt * Uu + yb] = s0 + by;
                out[(size_t)(b0 + 1) * Tt * Uu + yb] = s1 + by;
                out[(size_t)(b0 + 2) * Tt * Uu + yb] = s2 + by;
                out[(size_t)(b0 + 3) * Tt * Uu + yb] = s3 + by;
            }
        }
        __syncthreads();
    }

    // ---- epilogue: y_{Tt-1} from h_{Tt-1} (complete after final barrier) ----
    for (int i = tid; i < 512; i += 256) {
        int b = i >> 7, d4 = i & 127;
        ((float4*)h_s)[i] =
            *((const float4*)&g_xw[((size_t)(b0 + b) * Tt + (Tt - 1)) * Uu] + d4);
    }
    __syncthreads();
    if (tid < 128) {
        float4 a0 = make_float4(0.f, 0.f, 0.f, 0.f);
        float4 a1 = a0, a2 = a0, a3 = a0;
#pragma unroll
        for (int dd = 0; dd < 32; dd++) {
            float4 wv = wyr[dd];
            float4 h0v = h_s4[0 * 128 + qq * 32 + dd];
            float4 h1v = h_s4[1 * 128 + qq * 32 + dd];
            float4 h2v = h_s4[2 * 128 + qq * 32 + dd];
            float4 h3v = h_s4[3 * 128 + qq * 32 + dd];
            a0.x = fmaf(wv.x, h0v.x, a0.x); a0.y = fmaf(wv.y, h0v.y, a0.y);
            a0.z = fmaf(wv.z, h0v.z, a0.z); a0.w = fmaf(wv.w, h0v.w, a0.w);
            a1.x = fmaf(wv.x, h1v.x, a1.x); a1.y = fmaf(wv.y, h1v.y, a1.y);
            a1.z = fmaf(wv.z, h1v.z, a1.z); a1.w = fmaf(wv.w, h1v.w, a1.w);
            a2.x = fmaf(wv.x, h2v.x, a2.x); a2.y = fmaf(wv.y, h2v.y, a2.y);
            a2.z = fmaf(wv.z, h2v.z, a2.z); a2.w = fmaf(wv.w, h2v.w, a2.w);
            a3.x = fmaf(wv.x, h3v.x, a3.x); a3.y = fmaf(wv.y, h3v.y, a3.y);
            a3.z = fmaf(wv.z, h3v.z, a3.z); a3.w = fmaf(wv.w, h3v.w, a3.w);
        }
        float s0 = (a0.x + a0.y) + (a0.z + a0.w);
        float s1 = (a1.x + a1.y) + (a1.z + a1.w);
        float s2 = (a2.x + a2.y) + (a2.z + a2.w);
        float s3 = (a3.x + a3.y) + (a3.z + a3.w);
        s0 += __shfl_xor_sync(0xffffffffu, s0, 1);
        s0 += __shfl_xor_sync(0xffffffffu, s0, 2);
        s1 += __shfl_xor_sync(0xffffffffu, s1, 1);
        s1 += __shfl_xor_sync(0xffffffffu, s1, 2);
        s2 += __shfl_xor_sync(0xffffffffu, s2, 1);
        s2 += __shfl_xor_sync(0xffffffffu, s2, 2);
        s3 += __shfl_xor_sync(0xffffffffu, s3, 1);
        s3 += __shfl_xor_sync(0xffffffffu, s3, 2);
        if (qq == 0) {
            size_t yb = (size_t)(Tt - 1) * Uu + u0 + uy;
            out[(size_t)(b0 + 0) * Tt * Uu + yb] = s0 + by;
            out[(size_t)(b0 + 1) * Tt * Uu + yb] = s1 + by;
            out[(size_t)(b0 + 2) * Tt * Uu + yb] = s2 + by;
            out[(size_t)(b0 + 3) * Tt * Uu + yb] = s3 + by;
        }
    }
}

// ---------------------------------------------------------------------------
// h_final = H[:, T-1, :]
__global__ void copy_hfinal(float* __restrict__ out) {
    int i = blockIdx.x * 256 + threadIdx.x;
    if (i < Bz * Uu) {
        int b = i >> 9, u = i & 511;
        out[(size_t)Bz * Tt * Uu + i] =
            g_xw[((size_t)b * Tt + (Tt - 1)) * Uu + u];
    }
}

// ---------------------------------------------------------------------------
extern "C" void kernel_launch(void* const* d_in, const int* in_sizes, int n_in,
                              void* d_out, int out_size) {
    const float* x   = (const float*)d_in[0];
    const float* w_h = (const float*)d_in[1];
    const float* w_x = (const float*)d_in[2];
    const float* w_y = (const float*)d_in[3];
    const float* b_h = (const float*)d_in[4];
    const float* b_y = (const float*)d_in[5];
    const float* h0  = (const float*)d_in[6];
    float* out = (float*)d_out;

    float* xw = nullptr;
    unsigned int* ctr = nullptr;
    cudaGetSymbolAddress((void**)&xw, g_xw);
    cudaGetSymbolAddress((void**)&ctr, g_ctr);
    const int smem_scan = (16384 + 2048 + 1024 + 128 * 132) * 4;  // 147KB
    cudaFuncSetAttribute(rnn_scan8, cudaFuncAttributeMaxDynamicSharedMemorySize,
                         smem_scan);

    dim3 gg(4, 1024);

    // Phase 1: XW = x @ w_x + b_h  (also resets scan counters)
    sgemm_bias<<<gg, 256>>>(x, w_x, b_h, xw, ctr);
    // Phase 2+3 fused: scan computes H (in place over XW) and streams Y to out
    rnn_scan8<<<128, 256, smem_scan>>>(w_h, w_y, b_y, h0, out);
    // h_final = H[:, T-1, :]
    copy_hfinal<<<64, 256>>>(out);
}

// round 11
// speedup vs baseline: 1.7973x; 1.7973x over previous
#include <cuda_runtime.h>
#include <cstddef>
#include <cstdint>

#define Bz 32
#define Tt 4096
#define Uu 512

// 256MB scratch: holds XW = x@w_x + b_h, overwritten in place by H during scan.
__device__ float g_xw[(size_t)Bz * Tt * Uu];
// per-group monotonic counters (8 groups, 128B apart)
__device__ unsigned int g_ctr[8 * 32];

// ---------------------------------------------------------------------------
__device__ __forceinline__ float my_tanh(float x) {
    float ax = fabsf(x);
    if (ax < 0.125f) {
        float x2 = x * x;
        return x * (1.f + x2 * (-0.333333333f + x2 * 0.133333333f));
    }
    float e = __expf(2.f * ax);
    float r = 1.f - 2.f / (1.f + e);
    return copysignf(r, x);
}

// ---------------------------------------------------------------------------
// SGEMM with bias, double-buffered SMEM (one __syncthreads per BK chunk).
// C[M,512] = A[M,512] @ B[512,512] + bias[512]
// 128x128 tile, BK=16, 256 threads, 8x8 per thread.
// ---------------------------------------------------------------------------
__global__ __launch_bounds__(256) void sgemm_bias(
    const float* __restrict__ A, const float* __restrict__ Bm,
    const float* __restrict__ bias, float* __restrict__ C,
    unsigned int* __restrict__ rctr)
{
    __shared__ float As[2][16][132];
    __shared__ float Bs[2][16][128];
    const int tid = threadIdx.x;
    const int tx = tid & 15, ty = tid >> 4;
    const size_t row0 = (size_t)blockIdx.y * 128;
    const int col0 = blockIdx.x * 128;

    if (rctr && blockIdx.x == 0 && blockIdx.y == 0 && tid < 8)
        rctr[tid * 32] = 0u;

    // per-thread load slots: l=0,1 -> f = tid + l*256 in [0,512)
    const int f0 = tid, f1 = tid + 256;
    const int ar0 = f0 >> 2, ak0 = (f0 & 3) << 2;
    const int ar1 = f1 >> 2, ak1 = (f1 & 3) << 2;
    const int br0 = f0 >> 5, bc0 = (f0 & 31) << 2;
    const int br1 = f1 >> 5, bc1 = (f1 & 31) << 2;

    float4 pa0, pa1, pb0, pb1;

    // prologue: load chunk 0
    pa0 = *(const float4*)&A[(row0 + ar0) * 512 + 0 + ak0];
    pa1 = *(const float4*)&A[(row0 + ar1) * 512 + 0 + ak1];
    pb0 = *(const float4*)&Bm[(size_t)(0 + br0) * 512 + col0 + bc0];
    pb1 = *(const float4*)&Bm[(size_t)(0 + br1) * 512 + col0 + bc1];
    As[0][ak0 + 0][ar0] = pa0.x; As[0][ak0 + 1][ar0] = pa0.y;
    As[0][ak0 + 2][ar0] = pa0.z; As[0][ak0 + 3][ar0] = pa0.w;
    As[0][ak1 + 0][ar1] = pa1.x; As[0][ak1 + 1][ar1] = pa1.y;
    As[0][ak1 + 2][ar1] = pa1.z; As[0][ak1 + 3][ar1] = pa1.w;
    *(float4*)&Bs[0][br0][bc0] = pb0;
    *(float4*)&Bs[0][br1][bc1] = pb1;
    __syncthreads();

    float acc[8][8];
#pragma unroll
    for (int i = 0; i < 8; i++)
#pragma unroll
        for (int j = 0; j < 8; j++) acc[i][j] = 0.f;

    for (int k0 = 0; k0 < 512; k0 += 16) {
        const int cur = (k0 >> 4) & 1;
        const bool more = (k0 + 16) < 512;
        if (more) {   // issue next chunk's global loads (overlap with compute)
            pa0 = *(const float4*)&A[(row0 + ar0) * 512 + k0 + 16 + ak0];
            pa1 = *(const float4*)&A[(row0 + ar1) * 512 + k0 + 16 + ak1];
            pb0 = *(const float4*)&Bm[(size_t)(k0 + 16 + br0) * 512 + col0 + bc0];
            pb1 = *(const float4*)&Bm[(size_t)(k0 + 16 + br1) * 512 + col0 + bc1];
        }
#pragma unroll
        for (int k = 0; k < 16; k++) {
            float a[8], b[8];
            *(float4*)&a[0] = *(const float4*)&As[cur][k][ty * 8];
            *(float4*)&a[4] = *(const float4*)&As[cur][k][ty * 8 + 4];
            *(float4*)&b[0] = *(const float4*)&Bs[cur][k][tx * 8];
            *(float4*)&b[4] = *(const float4*)&Bs[cur][k][tx * 8 + 4];
#pragma unroll
            for (int i = 0; i < 8; i++)
#pragma unroll
                for (int j = 0; j < 8; j++)
                    acc[i][j] = fmaf(a[i], b[j], acc[i][j]);
        }
        if (more) {
            const int nxt = cur ^ 1;
            As[nxt][ak0 + 0][ar0] = pa0.x; As[nxt][ak0 + 1][ar0] = pa0.y;
            As[nxt][ak0 + 2][ar0] = pa0.z; As[nxt][ak0 + 3][ar0] = pa0.w;
            As[nxt][ak1 + 0][ar1] = pa1.x; As[nxt][ak1 + 1][ar1] = pa1.y;
            As[nxt][ak1 + 2][ar1] = pa1.z; As[nxt][ak1 + 3][ar1] = pa1.w;
            *(float4*)&Bs[nxt][br0][bc0] = pb0;
            *(float4*)&Bs[nxt][br1][bc1] = pb1;
            __syncthreads();
        }
    }

    float bj[8];
    *(float4*)&bj[0] = *(const float4*)&bias[col0 + tx * 8];
    *(float4*)&bj[4] = *(const float4*)&bias[col0 + tx * 8 + 4];
#pragma unroll
    for (int i = 0; i < 8; i++) {
        size_t r = row0 + ty * 8 + i;
        float4 v0 = make_float4(acc[i][0] + bj[0], acc[i][1] + bj[1],
                                acc[i][2] + bj[2], acc[i][3] + bj[3]);
        float4 v1 = make_float4(acc[i][4] + bj[4], acc[i][5] + bj[5],
                                acc[i][6] + bj[6], acc[i][7] + bj[7]);
        *(float4*)&C[r * 512 + col0 + tx * 8] = v0;
        *(float4*)&C[r * 512 + col0 + tx * 8 + 4] = v1;
    }
}

// ---------------------------------------------------------------------------
// Recurrent scan v9 = v7 (measured best) with ONE change: the barrier's
// __threadfence + atomicAdd replaced by a single red.release.gpu.add
// (pattern correctness-proven in the R6 bench). Poll unchanged.
// ---------------------------------------------------------------------------
__global__ __launch_bounds__(256) void rnn_scan9(const float* __restrict__ w_h,
                                                 const float* __restrict__ h0)
{
    extern __shared__ float smem[];
    float* w_s  = smem;                  // 512*32 = 16384 floats (64KB)
    float* h_s  = smem + 16384;          // 4*512  = 2048 floats
    float* psum = smem + 16384 + 2048;   // 8*128  = 1024 floats

    const int tid = threadIdx.x;
    const int grp = blockIdx.x >> 4;     // 0..7
    const int cig = blockIdx.x & 15;     // 0..15
    const int b0 = grp << 2;
    const int u0 = cig << 5;

    for (int i = tid; i < 16384; i += 256) {
        int d = i >> 5, j = i & 31;
        w_s[i] = w_h[d * 512 + u0 + j];
    }

    const int ut   = tid & 7;
    const int dcw  = tid >> 3;
    const int lane = tid & 31;
    const int warp = tid >> 5;
    const int d0q  = dcw << 2;
    const float4* w_s4 = (const float4*)w_s;   // [d*8 + ut]
    const float4* h_s4 = (const float4*)h_s;   // [b*128 + d4]
    unsigned int* ctr = &g_ctr[grp * 32];

    size_t oidx = 0;
    float xw_pf = 0.f;
    if (tid < 128) {
        int ul = tid >> 2, bq = tid & 3;
        oidx = ((size_t)(b0 + bq) * Tt) * Uu + u0 + ul;
        xw_pf = g_xw[oidx];              // xw for t = 0
    }

    __syncthreads();

    for (int t = 0; t < Tt; t++) {
        // ---- load h_{t-1} into SMEM (4 batches x 512) ----
        if (t == 0) {
            for (int i = tid; i < 2048; i += 256) h_s[i] = h0[i & 511];
        } else {
            for (int i = tid; i < 512; i += 256) {
                int b = i >> 7, d4 = i & 127;
                ((float4*)h_s)[i] =
                    *((const float4*)&g_xw[((size_t)(b0 + b) * Tt + (t - 1)) * Uu] + d4);
            }
        }
        __syncthreads();

        // ---- partial dot products: 4 units x 4 batches over 16 d ----
        float acc[16];
#pragma unroll
        for (int z = 0; z < 16; z++) acc[z] = 0.f;
#pragma unroll
        for (int i = 0; i < 4; i++) {
            float4 hv[4];
            hv[0] = h_s4[d0q + i];
            hv[1] = h_s4[128 + d0q + i];
            hv[2] = h_s4[256 + d0q + i];
            hv[3] = h_s4[384 + d0q + i];
#pragma unroll
            for (int j = 0; j < 4; j++) {
                float4 wv = w_s4[((d0q + i) * 4 + j) * 8 + ut];
                const float w0 = wv.x, w1 = wv.y, w2 = wv.z, w3 = wv.w;
#pragma unroll
                for (int b = 0; b < 4; b++) {
                    float hb = ((const float*)&hv[b])[j];
                    acc[b * 4 + 0] = fmaf(w0, hb, acc[b * 4 + 0]);
                    acc[b * 4 + 1] = fmaf(w1, hb, acc[b * 4 + 1]);
                    acc[b * 4 + 2] = fmaf(w2, hb, acc[b * 4 + 2]);
                    acc[b * 4 + 3] = fmaf(w3, hb, acc[b * 4 + 3]);
                }
            }
        }

        // ---- reduce over the 4 d-chunks within each warp (lane bits 3,4) ----
#pragma unroll
        for (int z = 0; z < 16; z++) {
            acc[z] += __shfl_xor_sync(0xffffffffu, acc[z], 8);
            acc[z] += __shfl_xor_sync(0xffffffffu, acc[z], 16);
        }
        if (lane < 8) {
#pragma unroll
            for (int uj = 0; uj < 4; uj++)
#pragma unroll
                for (int b = 0; b < 4; b++)
                    psum[warp * 128 + ((ut * 4 + uj) << 2) + b] = acc[b * 4 + uj];
        }
        __syncthreads();

        // ---- final reduce over 8 warps, tanh, write h_t in place over xw ----
        if (tid < 128) {
            float s = 0.f;
#pragma unroll
            for (int w = 0; w < 8; w++) s += psum[w * 128 + tid];
            float val = my_tanh(s + xw_pf);
            g_xw[oidx + (size_t)t * Uu] = val;
            if (t + 1 < Tt)   // prefetch next xw; latency hides under barrier
                xw_pf = g_xw[oidx + (size_t)(t + 1) * Uu];
        }
        __syncthreads();

        // ---- group barrier: release-add our arrival, spin for the 16 CTAs ----
        if (tid == 0) {
            asm volatile("red.release.gpu.global.add.u32 [%0], %1;"
                         :: "l"(ctr), "r"(1u) : "memory");
            unsigned int target = (unsigned int)(16 * (t + 1));
            unsigned int v;
            do {
                asm volatile("ld.global.acquire.gpu.u32 %0, [%1];"
                             : "=r"(v) : "l"(ctr));
            } while (v < target);
        }
        __syncthreads();
    }
}

// ---------------------------------------------------------------------------
// h_final = H[:, T-1, :]
__global__ void copy_hfinal(float* __restrict__ out) {
    int i = blockIdx.x * 256 + threadIdx.x;
    if (i < Bz * Uu) {
        int b = i >> 9, u = i & 511;
        out[(size_t)Bz * Tt * Uu + i] =
            g_xw[((size_t)b * Tt + (Tt - 1)) * Uu + u];
    }
}

// ---------------------------------------------------------------------------
extern "C" void kernel_launch(void* const* d_in, const int* in_sizes, int n_in,
                              void* d_out, int out_size) {
    const float* x   = (const float*)d_in[0];
    const float* w_h = (const float*)d_in[1];
    const float* w_x = (const float*)d_in[2];
    const float* w_y = (const float*)d_in[3];
    const float* b_h = (const float*)d_in[4];
    const float* b_y = (const float*)d_in[5];
    const float* h0  = (const float*)d_in[6];
    float* out = (float*)d_out;

    float* xw = nullptr;
    unsigned int* ctr = nullptr;
    cudaGetSymbolAddress((void**)&xw, g_xw);
    cudaGetSymbolAddress((void**)&ctr, g_ctr);
    const int smem_scan = (16384 + 2048 + 1024) * 4;
    cudaFuncSetAttribute(rnn_scan9, cudaFuncAttributeMaxDynamicSharedMemorySize,
                         smem_scan);

    dim3 gg(4, 1024);

    // Phase 1: XW = x @ w_x + b_h  (also resets scan counters)
    sgemm_bias<<<gg, 256>>>(x, w_x, b_h, xw, ctr);
    // Phase 2: sequential scan, H overwrites XW in place
    rnn_scan9<<<128, 256, smem_scan>>>(w_h, h0);
    // Phase 3: Y = H @ w_y + b_y
    sgemm_bias<<<gg, 256>>>(xw, w_y, b_y, out, nullptr);
    // h_final = H[:, T-1, :]
    copy_hfinal<<<64, 256>>>(out);
}

// round 12
// speedup vs baseline: 1.8532x; 1.0311x over previous
#include <cuda_runtime.h>
#include <cstddef>
#include <cstdint>

#define Bz 32
#define Tt 4096
#define Uu 512

typedef unsigned long long u64;

// 256MB scratch: holds XW = x@w_x + b_h, overwritten in place by H during scan.
__device__ float g_xw[(size_t)Bz * Tt * Uu];
// per-group monotonic counters (8 groups, 128B apart)
__device__ unsigned int g_ctr[8 * 32];

// ---------------------------------------------------------------------------
// Packed fp32x2 helpers (Blackwell packed-f32 path; exact fp32 per half)
// ---------------------------------------------------------------------------
__device__ __forceinline__ u64 pack1(float v) {
    u64 r; asm("mov.b64 %0, {%1, %1};" : "=l"(r) : "f"(v)); return r;
}
__device__ __forceinline__ void unpack2(float& lo, float& hi, u64 v) {
    asm("mov.b64 {%0, %1}, %2;" : "=f"(lo), "=f"(hi) : "l"(v));
}
__device__ __forceinline__ u64 ffma2(u64 a, u64 b, u64 c) {
    u64 d;
    asm("fma.rn.f32x2 %0, %1, %2, %3;" : "=l"(d) : "l"(a), "l"(b), "l"(c));
    return d;
}

// ---------------------------------------------------------------------------
__device__ __forceinline__ float my_tanh(float x) {
    float ax = fabsf(x);
    if (ax < 0.125f) {
        float x2 = x * x;
        return x * (1.f + x2 * (-0.333333333f + x2 * 0.133333333f));
    }
    float e = __expf(2.f * ax);
    float r = 1.f - 2.f / (1.f + e);
    return copysignf(r, x);
}

// ---------------------------------------------------------------------------
// SGEMM with bias, double-buffered SMEM, packed-fp32 (FFMA2) inner loop.
// C[M,512] = A[M,512] @ B[512,512] + bias[512]
// 128x128 tile, BK=16, 256 threads, 8 rows x 4 col-pairs per thread.
// ---------------------------------------------------------------------------
__global__ __launch_bounds__(256) void sgemm_bias(
    const float* __restrict__ A, const float* __restrict__ Bm,
    const float* __restrict__ bias, float* __restrict__ C,
    unsigned int* __restrict__ rctr)
{
    __shared__ float As[2][16][132];
    __shared__ float Bs[2][16][128];
    const int tid = threadIdx.x;
    const int tx = tid & 15, ty = tid >> 4;
    const size_t row0 = (size_t)blockIdx.y * 128;
    const int col0 = blockIdx.x * 128;

    if (rctr && blockIdx.x == 0 && blockIdx.y == 0 && tid < 8)
        rctr[tid * 32] = 0u;

    const int f0 = tid, f1 = tid + 256;
    const int ar0 = f0 >> 2, ak0 = (f0 & 3) << 2;
    const int ar1 = f1 >> 2, ak1 = (f1 & 3) << 2;
    const int br0 = f0 >> 5, bc0 = (f0 & 31) << 2;
    const int br1 = f1 >> 5, bc1 = (f1 & 31) << 2;

    float4 pa0, pa1, pb0, pb1;

    pa0 = *(const float4*)&A[(row0 + ar0) * 512 + 0 + ak0];
    pa1 = *(const float4*)&A[(row0 + ar1) * 512 + 0 + ak1];
    pb0 = *(const float4*)&Bm[(size_t)(0 + br0) * 512 + col0 + bc0];
    pb1 = *(const float4*)&Bm[(size_t)(0 + br1) * 512 + col0 + bc1];
    As[0][ak0 + 0][ar0] = pa0.x; As[0][ak0 + 1][ar0] = pa0.y;
    As[0][ak0 + 2][ar0] = pa0.z; As[0][ak0 + 3][ar0] = pa0.w;
    As[0][ak1 + 0][ar1] = pa1.x; As[0][ak1 + 1][ar1] = pa1.y;
    As[0][ak1 + 2][ar1] = pa1.z; As[0][ak1 + 3][ar1] = pa1.w;
    *(float4*)&Bs[0][br0][bc0] = pb0;
    *(float4*)&Bs[0][br1][bc1] = pb1;
    __syncthreads();

    u64 acc2[8][4];   // 8 rows x 4 col-pairs (cols 2p,2p+1)
#pragma unroll
    for (int i = 0; i < 8; i++)
#pragma unroll
        for (int p = 0; p < 4; p++) acc2[i][p] = pack1(0.f);

    for (int k0 = 0; k0 < 512; k0 += 16) {
        const int cur = (k0 >> 4) & 1;
        const bool more = (k0 + 16) < 512;
        if (more) {
            pa0 = *(const float4*)&A[(row0 + ar0) * 512 + k0 + 16 + ak0];
            pa1 = *(const float4*)&A[(row0 + ar1) * 512 + k0 + 16 + ak1];
            pb0 = *(const float4*)&Bm[(size_t)(k0 + 16 + br0) * 512 + col0 + bc0];
            pb1 = *(const float4*)&Bm[(size_t)(k0 + 16 + br1) * 512 + col0 + bc1];
        }
#pragma unroll
        for (int k = 0; k < 16; k++) {
            float a[8];
            *(float4*)&a[0] = *(const float4*)&As[cur][k][ty * 8];
            *(float4*)&a[4] = *(const float4*)&As[cur][k][ty * 8 + 4];
            ulonglong2 bq0 = *(const ulonglong2*)&Bs[cur][k][tx * 8];
            ulonglong2 bq1 = *(const ulonglong2*)&Bs[cur][k][tx * 8 + 4];
            u64 bp[4] = {bq0.x, bq0.y, bq1.x, bq1.y};
#pragma unroll
            for (int i = 0; i < 8; i++) {
                u64 ad = pack1(a[i]);
#pragma unroll
                for (int p = 0; p < 4; p++)
                    acc2[i][p] = ffma2(ad, bp[p], acc2[i][p]);
            }
        }
        if (more) {
            const int nxt = cur ^ 1;
            As[nxt][ak0 + 0][ar0] = pa0.x; As[nxt][ak0 + 1][ar0] = pa0.y;
            As[nxt][ak0 + 2][ar0] = pa0.z; As[nxt][ak0 + 3][ar0] = pa0.w;
            As[nxt][ak1 + 0][ar1] = pa1.x; As[nxt][ak1 + 1][ar1] = pa1.y;
            As[nxt][ak1 + 2][ar1] = pa1.z; As[nxt][ak1 + 3][ar1] = pa1.w;
            *(float4*)&Bs[nxt][br0][bc0] = pb0;
            *(float4*)&Bs[nxt][br1][bc1] = pb1;
            __syncthreads();
        }
    }

    float bj[8];
    *(float4*)&bj[0] = *(const float4*)&bias[col0 + tx * 8];
    *(float4*)&bj[4] = *(const float4*)&bias[col0 + tx * 8 + 4];
#pragma unroll
    for (int i = 0; i < 8; i++) {
        float c[8];
#pragma unroll
        for (int p = 0; p < 4; p++)
            unpack2(c[2 * p], c[2 * p + 1], acc2[i][p]);
        size_t r = row0 + ty * 8 + i;
        float4 v0 = make_float4(c[0] + bj[0], c[1] + bj[1],
                                c[2] + bj[2], c[3] + bj[3]);
        float4 v1 = make_float4(c[4] + bj[4], c[5] + bj[5],
                                c[6] + bj[6], c[7] + bj[7]);
        *(float4*)&C[r * 512 + col0 + tx * 8] = v0;
        *(float4*)&C[r * 512 + col0 + tx * 8 + 4] = v1;
    }
}

// ---------------------------------------------------------------------------
// Recurrent scan v10 = v9 (measured best) with the inner outer-product
// converted to packed fp32 (FFMA2): w unit-pairs come free from SMEM as
// ulonglong2; h scalars duplicated with one mov each. Bitwise-identical
// accumulation order; everything downstream unchanged.
// ---------------------------------------------------------------------------
__global__ __launch_bounds__(256) void rnn_scan10(const float* __restrict__ w_h,
                                                  const float* __restrict__ h0)
{
    extern __shared__ float smem[];
    float* w_s  = smem;                  // 512*32 = 16384 floats (64KB)
    float* h_s  = smem + 16384;          // 4*512  = 2048 floats
    float* psum = smem + 16384 + 2048;   // 8*128  = 1024 floats

    const int tid = threadIdx.x;
    const int grp = blockIdx.x >> 4;     // 0..7
    const int cig = blockIdx.x & 15;     // 0..15
    const int b0 = grp << 2;
    const int u0 = cig << 5;

    for (int i = tid; i < 16384; i += 256) {
        int d = i >> 5, j = i & 31;
        w_s[i] = w_h[d * 512 + u0 + j];
    }

    const int ut   = tid & 7;
    const int dcw  = tid >> 3;
    const int lane = tid & 31;
    const int warp = tid >> 5;
    const int d0q  = dcw << 2;
    const float4* h_s4 = (const float4*)h_s;   // [b*128 + d4]
    unsigned int* ctr = &g_ctr[grp * 32];

    size_t oidx = 0;
    float xw_pf = 0.f;
    if (tid < 128) {
        int ul = tid >> 2, bq = tid & 3;
        oidx = ((size_t)(b0 + bq) * Tt) * Uu + u0 + ul;
        xw_pf = g_xw[oidx];              // xw for t = 0
    }

    __syncthreads();

    for (int t = 0; t < Tt; t++) {
        // ---- load h_{t-1} into SMEM (4 batches x 512) ----
        if (t == 0) {
            for (int i = tid; i < 2048; i += 256) h_s[i] = h0[i & 511];
        } else {
            for (int i = tid; i < 512; i += 256) {
                int b = i >> 7, d4 = i & 127;
                ((float4*)h_s)[i] =
                    *((const float4*)&g_xw[((size_t)(b0 + b) * Tt + (t - 1)) * Uu] + d4);
            }
        }
        __syncthreads();

        // ---- packed partial dot products: 2 unit-pairs x 4 batches x 16 d ----
        u64 acc2[4][2];                   // [batch][unit-pair]
#pragma unroll
        for (int b = 0; b < 4; b++) {
            acc2[b][0] = pack1(0.f);
            acc2[b][1] = pack1(0.f);
        }
#pragma unroll
        for (int i = 0; i < 4; i++) {
            float4 hv[4];
            hv[0] = h_s4[d0q + i];
            hv[1] = h_s4[128 + d0q + i];
            hv[2] = h_s4[256 + d0q + i];
            hv[3] = h_s4[384 + d0q + i];
#pragma unroll
            for (int j = 0; j < 4; j++) {
                ulonglong2 wv2 = *(const ulonglong2*)
                    &w_s[(((d0q + i) * 4 + j) * 8 + ut) * 4];
#pragma unroll
                for (int b = 0; b < 4; b++) {
                    u64 hd = pack1(((const float*)&hv[b])[j]);
                    acc2[b][0] = ffma2(hd, wv2.x, acc2[b][0]);
                    acc2[b][1] = ffma2(hd, wv2.y, acc2[b][1]);
                }
            }
        }

        // ---- unpack to the v7 scalar layout acc[b*4 + uj] ----
        float acc[16];
#pragma unroll
        for (int b = 0; b < 4; b++) {
            unpack2(acc[b * 4 + 0], acc[b * 4 + 1], acc2[b][0]);
            unpack2(acc[b * 4 + 2], acc[b * 4 + 3], acc2[b][1]);
        }

        // ---- reduce over the 4 d-chunks within each warp (lane bits 3,4) ----
#pragma unroll
        for (int z = 0; z < 16; z++) {
            acc[z] += __shfl_xor_sync(0xffffffffu, acc[z], 8);
            acc[z] += __shfl_xor_sync(0xffffffffu, acc[z], 16);
        }
        if (lane < 8) {
#pragma unroll
            for (int uj = 0; uj < 4; uj++)
#pragma unroll
                for (int b = 0; b < 4; b++)
                    psum[warp * 128 + ((ut * 4 + uj) << 2) + b] = acc[b * 4 + uj];
        }
        __syncthreads();

        // ---- final reduce over 8 warps, tanh, write h_t in place over xw ----
        if (tid < 128) {
            float s = 0.f;
#pragma unroll
            for (int w = 0; w < 8; w++) s += psum[w * 128 + tid];
            float val = my_tanh(s + xw_pf);
            g_xw[oidx + (size_t)t * Uu] = val;
            if (t + 1 < Tt)   // prefetch next xw; latency hides under barrier
                xw_pf = g_xw[oidx + (size_t)(t + 1) * Uu];
        }
        __syncthreads();

        // ---- group barrier: release-add our arrival, spin for the 16 CTAs ----
        if (tid == 0) {
            asm volatile("red.release.gpu.global.add.u32 [%0], %1;"
                         :: "l"(ctr), "r"(1u) : "memory");
            unsigned int target = (unsigned int)(16 * (t + 1));
            unsigned int v;
            do {
                asm volatile("ld.global.acquire.gpu.u32 %0, [%1];"
                             : "=r"(v) : "l"(ctr));
            } while (v < target);
        }
        __syncthreads();
    }
}

// ---------------------------------------------------------------------------
// h_final = H[:, T-1, :]
__global__ void copy_hfinal(float* __restrict__ out) {
    int i = blockIdx.x * 256 + threadIdx.x;
    if (i < Bz * Uu) {
        int b = i >> 9, u = i & 511;
        out[(size_t)Bz * Tt * Uu + i] =
            g_xw[((size_t)b * Tt + (Tt - 1)) * Uu + u];
    }
}

// ---------------------------------------------------------------------------
extern "C" void kernel_launch(void* const* d_in, const int* in_sizes, int n_in,
                              void* d_out, int out_size) {
    const float* x   = (const float*)d_in[0];
    const float* w_h = (const float*)d_in[1];
    const float* w_x = (const float*)d_in[2];
    const float* w_y = (const float*)d_in[3];
    const float* b_h = (const float*)d_in[4];
    const float* b_y = (const float*)d_in[5];
    const float* h0  = (const float*)d_in[6];
    float* out = (float*)d_out;

    float* xw = nullptr;
    unsigned int* ctr = nullptr;
    cudaGetSymbolAddress((void**)&xw, g_xw);
    cudaGetSymbolAddress((void**)&ctr, g_ctr);
    const int smem_scan = (16384 + 2048 + 1024) * 4;
    cudaFuncSetAttribute(rnn_scan10, cudaFuncAttributeMaxDynamicSharedMemorySize,
                         smem_scan);

    dim3 gg(4, 1024);

    // Phase 1: XW = x @ w_x + b_h  (also resets scan counters)
    sgemm_bias<<<gg, 256>>>(x, w_x, b_h, xw, ctr);
    // Phase 2: sequential scan, H overwrites XW in place
    rnn_scan10<<<128, 256, smem_scan>>>(w_h, h0);
    // Phase 3: Y = H @ w_y + b_y
    sgemm_bias<<<gg, 256>>>(xw, w_y, b_y, out, nullptr);
    // h_final = H[:, T-1, :]
    copy_hfinal<<<64, 256>>>(out);
}

// round 14
// speedup vs baseline: 1.9754x; 1.0659x over previous
#include <cuda_runtime.h>
#include <cstddef>
#include <cstdint>

#define Bz 32
#define Tt 4096
#define Uu 512

typedef unsigned long long u64;

// 256MB scratch: holds XW = x@w_x + b_h, overwritten in place by H during scan.
__device__ float g_xw[(size_t)Bz * Tt * Uu];
// per-group monotonic counters (16 groups, 128B apart)
__device__ unsigned int g_ctr[16 * 32];

// ---------------------------------------------------------------------------
// Packed fp32x2 helpers
// ---------------------------------------------------------------------------
__device__ __forceinline__ u64 pack1(float v) {
    u64 r; asm("mov.b64 %0, {%1, %1};" : "=l"(r) : "f"(v)); return r;
}
__device__ __forceinline__ void unpack2(float& lo, float& hi, u64 v) {
    asm("mov.b64 {%0, %1}, %2;" : "=f"(lo), "=f"(hi) : "l"(v));
}
__device__ __forceinline__ u64 ffma2(u64 a, u64 b, u64 c) {
    u64 d;
    asm("fma.rn.f32x2 %0, %1, %2, %3;" : "=l"(d) : "l"(a), "l"(b), "l"(c));
    return d;
}

__device__ __forceinline__ float my_tanh(float x) {
    float ax = fabsf(x);
    if (ax < 0.125f) {
        float x2 = x * x;
        return x * (1.f + x2 * (-0.333333333f + x2 * 0.133333333f));
    }
    float e = __expf(2.f * ax);
    float r = 1.f - 2.f / (1.f + e);
    return copysignf(r, x);
}

// ---------------------------------------------------------------------------
// SGEMM with bias, double-buffered SMEM, packed-fp32 (FFMA2) inner loop.
// (R12 proven version; counter reset covers 16 groups now.)
// ---------------------------------------------------------------------------
__global__ __launch_bounds__(256) void sgemm_bias(
    const float* __restrict__ A, const float* __restrict__ Bm,
    const float* __restrict__ bias, float* __restrict__ C,
    unsigned int* __restrict__ rctr)
{
    __shared__ float As[2][16][132];
    __shared__ float Bs[2][16][128];
    const int tid = threadIdx.x;
    const int tx = tid & 15, ty = tid >> 4;
    const size_t row0 = (size_t)blockIdx.y * 128;
    const int col0 = blockIdx.x * 128;

    if (rctr && blockIdx.x == 0 && blockIdx.y == 0 && tid < 16)
        rctr[tid * 32] = 0u;

    const int f0 = tid, f1 = tid + 256;
    const int ar0 = f0 >> 2, ak0 = (f0 & 3) << 2;
    const int ar1 = f1 >> 2, ak1 = (f1 & 3) << 2;
    const int br0 = f0 >> 5, bc0 = (f0 & 31) << 2;
    const int br1 = f1 >> 5, bc1 = (f1 & 31) << 2;

    float4 pa0, pa1, pb0, pb1;

    pa0 = *(const float4*)&A[(row0 + ar0) * 512 + 0 + ak0];
    pa1 = *(const float4*)&A[(row0 + ar1) * 512 + 0 + ak1];
    pb0 = *(const float4*)&Bm[(size_t)(0 + br0) * 512 + col0 + bc0];
    pb1 = *(const float4*)&Bm[(size_t)(0 + br1) * 512 + col0 + bc1];
    As[0][ak0 + 0][ar0] = pa0.x; As[0][ak0 + 1][ar0] = pa0.y;
    As[0][ak0 + 2][ar0] = pa0.z; As[0][ak0 + 3][ar0] = pa0.w;
    As[0][ak1 + 0][ar1] = pa1.x; As[0][ak1 + 1][ar1] = pa1.y;
    As[0][ak1 + 2][ar1] = pa1.z; As[0][ak1 + 3][ar1] = pa1.w;
    *(float4*)&Bs[0][br0][bc0] = pb0;
    *(float4*)&Bs[0][br1][bc1] = pb1;
    __syncthreads();

    u64 acc2[8][4];
#pragma unroll
    for (int i = 0; i < 8; i++)
#pragma unroll
        for (int p = 0; p < 4; p++) acc2[i][p] = pack1(0.f);

    for (int k0 = 0; k0 < 512; k0 += 16) {
        const int cur = (k0 >> 4) & 1;
        const bool more = (k0 + 16) < 512;
        if (more) {
            pa0 = *(const float4*)&A[(row0 + ar0) * 512 + k0 + 16 + ak0];
            pa1 = *(const float4*)&A[(row0 + ar1) * 512 + k0 + 16 + ak1];
            pb0 = *(const float4*)&Bm[(size_t)(k0 + 16 + br0) * 512 + col0 + bc0];
            pb1 = *(const float4*)&Bm[(size_t)(k0 + 16 + br1) * 512 + col0 + bc1];
        }
#pragma unroll
        for (int k = 0; k < 16; k++) {
            float a[8];
            *(float4*)&a[0] = *(const float4*)&As[cur][k][ty * 8];
            *(float4*)&a[4] = *(const float4*)&As[cur][k][ty * 8 + 4];
            ulonglong2 bq0 = *(const ulonglong2*)&Bs[cur][k][tx * 8];
            ulonglong2 bq1 = *(const ulonglong2*)&Bs[cur][k][tx * 8 + 4];
            u64 bp[4] = {bq0.x, bq0.y, bq1.x, bq1.y};
#pragma unroll
            for (int i = 0; i < 8; i++) {
                u64 ad = pack1(a[i]);
#pragma unroll
                for (int p = 0; p < 4; p++)
                    acc2[i][p] = ffma2(ad, bp[p], acc2[i][p]);
            }
        }
        if (more) {
            const int nxt = cur ^ 1;
            As[nxt][ak0 + 0][ar0] = pa0.x; As[nxt][ak0 + 1][ar0] = pa0.y;
            As[nxt][ak0 + 2][ar0] = pa0.z; As[nxt][ak0 + 3][ar0] = pa0.w;
            As[nxt][ak1 + 0][ar1] = pa1.x; As[nxt][ak1 + 1][ar1] = pa1.y;
            As[nxt][ak1 + 2][ar1] = pa1.z; As[nxt][ak1 + 3][ar1] = pa1.w;
            *(float4*)&Bs[nxt][br0][bc0] = pb0;
            *(float4*)&Bs[nxt][br1][bc1] = pb1;
            __syncthreads();
        }
    }

    float bj[8];
    *(float4*)&bj[0] = *(const float4*)&bias[col0 + tx * 8];
    *(float4*)&bj[4] = *(const float4*)&bias[col0 + tx * 8 + 4];
#pragma unroll
    for (int i = 0; i < 8; i++) {
        float c[8];
#pragma unroll
        for (int p = 0; p < 4; p++)
            unpack2(c[2 * p], c[2 * p + 1], acc2[i][p]);
        size_t r = row0 + ty * 8 + i;
        float4 v0 = make_float4(c[0] + bj[0], c[1] + bj[1],
                                c[2] + bj[2], c[3] + bj[3]);
        float4 v1 = make_float4(c[4] + bj[4], c[5] + bj[5],
                                c[6] + bj[6], c[7] + bj[7]);
        *(float4*)&C[r * 512 + col0 + tx * 8] = v0;
        *(float4*)&C[r * 512 + col0 + tx * 8 + 4] = v1;
    }
}

// ---------------------------------------------------------------------------
// Recurrent scan v11 = v10's machinery, occupancy-2 variant.
// 16 groups x 16 CTAs = 256 CTAs, 2 CTAs per SM (all co-resident: 296 slots).
// Group g owns batches {2g, 2g+1}; CTA c-in-group owns units [32c, 32c+32).
// While one CTA spins at the group barrier, the co-resident CTA computes —
// hiding barrier latency. Per-output arithmetic identical to v10.
// SMEM/CTA: w 64KB + h 4KB + psum 2KB = 70KB (2 fit in 228KB).
// ---------------------------------------------------------------------------
__global__ __launch_bounds__(256, 2) void rnn_scan11(
    const float* __restrict__ w_h, const float* __restrict__ h0)
{
    extern __shared__ float smemf[];
    float* w_s  = smemf;                 // 512*32 = 16384 floats
    float* h_s  = smemf + 16384;         // 2*512  = 1024 floats
    float* psum = smemf + 16384 + 1024;  // 8*64   = 512 floats

    const int tid = threadIdx.x;
    const int grp = blockIdx.x >> 4;     // 0..15
    const int cig = blockIdx.x & 15;     // 0..15
    const int b0 = grp << 1;             // 2 batches per group
    const int u0 = cig << 5;

    for (int i = tid; i < 16384; i += 256) {
        int d = i >> 5, j = i & 31;
        w_s[i] = w_h[d * 512 + u0 + j];
    }

    const int ut   = tid & 7;
    const int dcw  = tid >> 3;
    const int lane = tid & 31;
    const int warp = tid >> 5;
    const int d0q  = dcw << 2;
    const float4* h_s4 = (const float4*)h_s;   // [b*128 + d4]
    unsigned int* ctr = &g_ctr[grp * 32];

    // writer threads (tid < 64): output = (unit ul, batch bq)
    size_t oidx = 0;
    float xw_pf = 0.f;
    if (tid < 64) {
        int ul = tid >> 1, bq = tid & 1;
        oidx = ((size_t)(b0 + bq) * Tt) * Uu + u0 + ul;
        xw_pf = g_xw[oidx];              // xw for t = 0
    }

    __syncthreads();

    for (int t = 0; t < Tt; t++) {
        // ---- load h_{t-1} into SMEM (2 batches x 512) ----
        if (t == 0) {
            for (int i = tid; i < 1024; i += 256) h_s[i] = h0[i & 511];
        } else {
            int b = tid >> 7, d4 = tid & 127;
            ((float4*)h_s)[tid] =
                *((const float4*)&g_xw[((size_t)(b0 + b) * Tt + (t - 1)) * Uu] + d4);
        }
        __syncthreads();

        // ---- packed partial dot products: 2 unit-pairs x 2 batches x 16 d ----
        u64 acc2[2][2];                   // [batch][unit-pair]
        acc2[0][0] = pack1(0.f); acc2[0][1] = pack1(0.f);
        acc2[1][0] = pack1(0.f); acc2[1][1] = pack1(0.f);
#pragma unroll
        for (int i = 0; i < 4; i++) {
            float4 hv0 = h_s4[d0q + i];
            float4 hv1 = h_s4[128 + d0q + i];
#pragma unroll
            for (int j = 0; j < 4; j++) {
                ulonglong2 wv2 = *(const ulonglong2*)
                    &w_s[(((d0q + i) * 4 + j) * 8 + ut) * 4];
                u64 hd0 = pack1(((const float*)&hv0)[j]);
                u64 hd1 = pack1(((const float*)&hv1)[j]);
                acc2[0][0] = ffma2(hd0, wv2.x, acc2[0][0]);
                acc2[0][1] = ffma2(hd0, wv2.y, acc2[0][1]);
                acc2[1][0] = ffma2(hd1, wv2.x, acc2[1][0]);
                acc2[1][1] = ffma2(hd1, wv2.y, acc2[1][1]);
            }
        }

        // ---- unpack: acc[b*4 + uj] ----
        float acc[8];
        unpack2(acc[0], acc[1], acc2[0][0]);
        unpack2(acc[2], acc[3], acc2[0][1]);
        unpack2(acc[4], acc[5], acc2[1][0]);
        unpack2(acc[6], acc[7], acc2[1][1]);

        // ---- reduce over the 4 d-chunks within each warp (lane bits 3,4) ----
#pragma unroll
        for (int z = 0; z < 8; z++) {
            acc[z] += __shfl_xor_sync(0xffffffffu, acc[z], 8);
            acc[z] += __shfl_xor_sync(0xffffffffu, acc[z], 16);
        }
        if (lane < 8) {
#pragma unroll
            for (int uj = 0; uj < 4; uj++)
#pragma unroll
                for (int b = 0; b < 2; b++)
                    psum[warp * 64 + ((ut * 4 + uj) << 1) + b] = acc[b * 4 + uj];
        }
        __syncthreads();

        // ---- final reduce over 8 warps, tanh, write h_t in place over xw ----
        if (tid < 64) {
            float s = 0.f;
#pragma unroll
            for (int w = 0; w < 8; w++) s += psum[w * 64 + tid];
            float val = my_tanh(s + xw_pf);
            g_xw[oidx + (size_t)t * Uu] = val;
            if (t + 1 < Tt)   // prefetch next xw; latency hides under barrier
                xw_pf = g_xw[oidx + (size_t)(t + 1) * Uu];
        }
        __syncthreads();

        // ---- group barrier: release-add our arrival, spin for the 16 CTAs ----
        if (tid == 0) {
            asm volatile("red.release.gpu.global.add.u32 [%0], %1;"
                         :: "l"(ctr), "r"(1u) : "memory");
            unsigned int target = (unsigned int)(16 * (t + 1));
            unsigned int v;
            do {
                asm volatile("ld.global.acquire.gpu.u32 %0, [%1];"
                             : "=r"(v) : "l"(ctr));
            } while (v < target);
        }
        __syncthreads();
    }
}

// ---------------------------------------------------------------------------
// h_final = H[:, T-1, :]
__global__ void copy_hfinal(float* __restrict__ out) {
    int i = blockIdx.x * 256 + threadIdx.x;
    if (i < Bz * Uu) {
        int b = i >> 9, u = i & 511;
        out[(size_t)Bz * Tt * Uu + i] =
            g_xw[((size_t)b * Tt + (Tt - 1)) * Uu + u];
    }
}

// ---------------------------------------------------------------------------
extern "C" void kernel_launch(void* const* d_in, const int* in_sizes, int n_in,
                              void* d_out, int out_size) {
    const float* x   = (const float*)d_in[0];
    const float* w_h = (const float*)d_in[1];
    const float* w_x = (const float*)d_in[2];
    const float* w_y = (const float*)d_in[3];
    const float* b_h = (const float*)d_in[4];
    const float* b_y = (const float*)d_in[5];
    const float* h0  = (const float*)d_in[6];
    float* out = (float*)d_out;

    float* xw = nullptr;
    unsigned int* ctr = nullptr;
    cudaGetSymbolAddress((void**)&xw, g_xw);
    cudaGetSymbolAddress((void**)&ctr, g_ctr);
    const int smem_scan = (16384 + 1024 + 512) * 4;   // 71680 B -> 2 CTAs/SM
    cudaFuncSetAttribute(rnn_scan11, cudaFuncAttributeMaxDynamicSharedMemorySize,
                         smem_scan);

    dim3 gg(4, 1024);

    // Phase 1: XW = x @ w_x + b_h  (also resets the 16 scan counters)
    sgemm_bias<<<gg, 256>>>(x, w_x, b_h, xw, ctr);
    // Phase 2: sequential scan (256 CTAs, 2/SM), H overwrites XW in place
    rnn_scan11<<<256, 256, smem_scan>>>(w_h, h0);
    // Phase 3: Y = H @ w_y + b_y
    sgemm_bias<<<gg, 256>>>(xw, w_y, b_y, out, nullptr);
    // h_final = H[:, T-1, :]
    copy_hfinal<<<64, 256>>>(out);
}

// round 15
// speedup vs baseline: 2.0161x; 1.0206x over previous
#include <cuda_runtime.h>
#include <cstddef>
#include <cstdint>

#define Bz 32
#define Tt 4096
#define Uu 512

typedef unsigned long long u64;

// 256MB scratch: holds XW = x@w_x + b_h, overwritten in place by H during scan.
__device__ float g_xw[(size_t)Bz * Tt * Uu];
// per-group monotonic counters (8 groups used, 128B apart)
__device__ unsigned int g_ctr[16 * 32];

// ---------------------------------------------------------------------------
// Packed fp32x2 helpers
// ---------------------------------------------------------------------------
__device__ __forceinline__ u64 pack1(float v) {
    u64 r; asm("mov.b64 %0, {%1, %1};" : "=l"(r) : "f"(v)); return r;
}
__device__ __forceinline__ void unpack2(float& lo, float& hi, u64 v) {
    asm("mov.b64 {%0, %1}, %2;" : "=f"(lo), "=f"(hi) : "l"(v));
}
__device__ __forceinline__ u64 ffma2(u64 a, u64 b, u64 c) {
    u64 d;
    asm("fma.rn.f32x2 %0, %1, %2, %3;" : "=l"(d) : "l"(a), "l"(b), "l"(c));
    return d;
}
__device__ __forceinline__ u64 add2(u64 a, u64 b) {
    u64 d;
    asm("add.rn.f32x2 %0, %1, %2;" : "=l"(d) : "l"(a), "l"(b));
    return d;
}

__device__ __forceinline__ float my_tanh(float x) {
    float ax = fabsf(x);
    if (ax < 0.125f) {
        float x2 = x * x;
        return x * (1.f + x2 * (-0.333333333f + x2 * 0.133333333f));
    }
    float e = __expf(2.f * ax);
    float r = 1.f - 2.f / (1.f + e);
    return copysignf(r, x);
}

// ---------------------------------------------------------------------------
// SGEMM with bias, double-buffered SMEM, packed-fp32 (FFMA2) inner loop.
// (R14 proven version.)
// ---------------------------------------------------------------------------
__global__ __launch_bounds__(256) void sgemm_bias(
    const float* __restrict__ A, const float* __restrict__ Bm,
    const float* __restrict__ bias, float* __restrict__ C,
    unsigned int* __restrict__ rctr)
{
    __shared__ float As[2][16][132];
    __shared__ float Bs[2][16][128];
    const int tid = threadIdx.x;
    const int tx = tid & 15, ty = tid >> 4;
    const size_t row0 = (size_t)blockIdx.y * 128;
    const int col0 = blockIdx.x * 128;

    if (rctr && blockIdx.x == 0 && blockIdx.y == 0 && tid < 16)
        rctr[tid * 32] = 0u;

    const int f0 = tid, f1 = tid + 256;
    const int ar0 = f0 >> 2, ak0 = (f0 & 3) << 2;
    const int ar1 = f1 >> 2, ak1 = (f1 & 3) << 2;
    const int br0 = f0 >> 5, bc0 = (f0 & 31) << 2;
    const int br1 = f1 >> 5, bc1 = (f1 & 31) << 2;

    float4 pa0, pa1, pb0, pb1;

    pa0 = *(const float4*)&A[(row0 + ar0) * 512 + 0 + ak0];
    pa1 = *(const float4*)&A[(row0 + ar1) * 512 + 0 + ak1];
    pb0 = *(const float4*)&Bm[(size_t)(0 + br0) * 512 + col0 + bc0];
    pb1 = *(const float4*)&Bm[(size_t)(0 + br1) * 512 + col0 + bc1];
    As[0][ak0 + 0][ar0] = pa0.x; As[0][ak0 + 1][ar0] = pa0.y;
    As[0][ak0 + 2][ar0] = pa0.z; As[0][ak0 + 3][ar0] = pa0.w;
    As[0][ak1 + 0][ar1] = pa1.x; As[0][ak1 + 1][ar1] = pa1.y;
    As[0][ak1 + 2][ar1] = pa1.z; As[0][ak1 + 3][ar1] = pa1.w;
    *(float4*)&Bs[0][br0][bc0] = pb0;
    *(float4*)&Bs[0][br1][bc1] = pb1;
    __syncthreads();

    u64 acc2[8][4];
#pragma unroll
    for (int i = 0; i < 8; i++)
#pragma unroll
        for (int p = 0; p < 4; p++) acc2[i][p] = pack1(0.f);

    for (int k0 = 0; k0 < 512; k0 += 16) {
        const int cur = (k0 >> 4) & 1;
        const bool more = (k0 + 16) < 512;
        if (more) {
            pa0 = *(const float4*)&A[(row0 + ar0) * 512 + k0 + 16 + ak0];
            pa1 = *(const float4*)&A[(row0 + ar1) * 512 + k0 + 16 + ak1];
            pb0 = *(const float4*)&Bm[(size_t)(k0 + 16 + br0) * 512 + col0 + bc0];
            pb1 = *(const float4*)&Bm[(size_t)(k0 + 16 + br1) * 512 + col0 + bc1];
        }
#pragma unroll
        for (int k = 0; k < 16; k++) {
            float a[8];
            *(float4*)&a[0] = *(const float4*)&As[cur][k][ty * 8];
            *(float4*)&a[4] = *(const float4*)&As[cur][k][ty * 8 + 4];
            ulonglong2 bq0 = *(const ulonglong2*)&Bs[cur][k][tx * 8];
            ulonglong2 bq1 = *(const ulonglong2*)&Bs[cur][k][tx * 8 + 4];
            u64 bp[4] = {bq0.x, bq0.y, bq1.x, bq1.y};
#pragma unroll
            for (int i = 0; i < 8; i++) {
                u64 ad = pack1(a[i]);
#pragma unroll
                for (int p = 0; p < 4; p++)
                    acc2[i][p] = ffma2(ad, bp[p], acc2[i][p]);
            }
        }
        if (more) {
            const int nxt = cur ^ 1;
            As[nxt][ak0 + 0][ar0] = pa0.x; As[nxt][ak0 + 1][ar0] = pa0.y;
            As[nxt][ak0 + 2][ar0] = pa0.z; As[nxt][ak0 + 3][ar0] = pa0.w;
            As[nxt][ak1 + 0][ar1] = pa1.x; As[nxt][ak1 + 1][ar1] = pa1.y;
            As[nxt][ak1 + 2][ar1] = pa1.z; As[nxt][ak1 + 3][ar1] = pa1.w;
            *(float4*)&Bs[nxt][br0][bc0] = pb0;
            *(float4*)&Bs[nxt][br1][bc1] = pb1;
            __syncthreads();
        }
    }

    float bj[8];
    *(float4*)&bj[0] = *(const float4*)&bias[col0 + tx * 8];
    *(float4*)&bj[4] = *(const float4*)&bias[col0 + tx * 8 + 4];
#pragma unroll
    for (int i = 0; i < 8; i++) {
        float c[8];
#pragma unroll
        for (int p = 0; p < 4; p++)
            unpack2(c[2 * p], c[2 * p + 1], acc2[i][p]);
        size_t r = row0 + ty * 8 + i;
        float4 v0 = make_float4(c[0] + bj[0], c[1] + bj[1],
                                c[2] + bj[2], c[3] + bj[3]);
        float4 v1 = make_float4(c[4] + bj[4], c[5] + bj[5],
                                c[6] + bj[6], c[7] + bj[7]);
        *(float4*)&C[r * 512 + col0 + tx * 8] = v0;
        *(float4*)&C[r * 512 + col0 + tx * 8 + 4] = v1;
    }
}

// ---------------------------------------------------------------------------
// Recurrent scan v12: register-resident w + broadcast h.
// 8 groups x 16 CTAs (128 CTAs, occ 1, all co-resident). Group g owns
// batches [4g,4g+4); CTA c owns units [32c,32c+32).
// Warp w owns d in [64w, 64w+64); lane = unit. Each thread keeps its 64
// w values pre-packed (w,w) in registers. h staged per step as
// hp_s[d] = (h[b0][d], h[b1][d], h[b2][d], h[b3][d]) — inner loop is one
// broadcast LDS.128 + two FFMA2 per d: crossbar ~0, no shuffles.
// Cross-warp reduce via psum2; tail + barrier = proven v7/v10 machinery.
// ---------------------------------------------------------------------------
__global__ __launch_bounds__(256, 1) void rnn_scan12(
    const float* __restrict__ w_h, const float* __restrict__ h0)
{
    __shared__ float4 hp_s[512];          // 8KB: (b0,b1,b2,b3) per d
    __shared__ ulonglong2 psum2[256];     // 4KB: [warp*32 + lane]

    const int tid  = threadIdx.x;
    const int warp = tid >> 5;
    const int lane = tid & 31;
    const int grp  = blockIdx.x >> 4;     // 0..7
    const int cig  = blockIdx.x & 15;     // 0..15
    const int b0   = grp << 2;
    const int u0   = cig << 5;

    // ---- load this thread's 64 w values into pre-packed registers ----
    u64 wreg[64];
#pragma unroll
    for (int j = 0; j < 64; j++)
        wreg[j] = pack1(w_h[(size_t)(warp * 64 + j) * 512 + u0 + lane]);

    unsigned int* ctr = &g_ctr[grp * 32];

    // writer threads (tid < 128): output = (unit ul, batch bq)
    size_t oidx = 0;
    float xw_pf = 0.f;
    if (tid < 128) {
        int ul = tid >> 2, bq = tid & 3;
        oidx = ((size_t)(b0 + bq) * Tt) * Uu + u0 + ul;
        xw_pf = g_xw[oidx];               // xw for t = 0
    }
    __syncthreads();

    for (int t = 0; t < Tt; t++) {
        // ---- stage h_{t-1} as batch-quads ----
        if (t == 0) {
#pragma unroll
            for (int r = 0; r < 2; r++) {
                int d = tid + r * 256;
                float v = h0[d];
                hp_s[d] = make_float4(v, v, v, v);
            }
        } else {
#pragma unroll
            for (int r = 0; r < 2; r++) {
                int d = tid + r * 256;
                size_t rb = (size_t)(t - 1) * Uu + d;
                hp_s[d] = make_float4(
                    g_xw[(size_t)(b0 + 0) * Tt * Uu + rb],
                    g_xw[(size_t)(b0 + 1) * Tt * Uu + rb],
                    g_xw[(size_t)(b0 + 2) * Tt * Uu + rb],
                    g_xw[(size_t)(b0 + 3) * Tt * Uu + rb]);
            }
        }
        __syncthreads();

        // ---- broadcast-h FFMA2 dot: 64 d per thread, ILP-2 split ----
        const ulonglong2* hp = (const ulonglong2*)&hp_s[warp * 64];
        u64 a01a = pack1(0.f), a01b = pack1(0.f);
        u64 a23a = pack1(0.f), a23b = pack1(0.f);
#pragma unroll
        for (int j = 0; j < 64; j += 2) {
            ulonglong2 q0 = hp[j];
            ulonglong2 q1 = hp[j + 1];
            a01a = ffma2(wreg[j], q0.x, a01a);
            a23a = ffma2(wreg[j], q0.y, a23a);
            a01b = ffma2(wreg[j + 1], q1.x, a01b);
            a23b = ffma2(wreg[j + 1], q1.y, a23b);
        }
        ulonglong2 mine;
        mine.x = add2(a01a, a01b);
        mine.y = add2(a23a, a23b);
        psum2[warp * 32 + lane] = mine;
        __syncthreads();

        // ---- final reduce over 8 warps, tanh, persist h_t, prefetch xw ----
        if (tid < 128) {
            const float* pf = (const float*)psum2;  // idx: w*128 + ul*4 + bq
            float s = 0.f;
#pragma unroll
            for (int w = 0; w < 8; w++) s += pf[w * 128 + tid];
            float val = my_tanh(s + xw_pf);
            g_xw[oidx + (size_t)t * Uu] = val;
            if (t + 1 < Tt)   // prefetch next xw; latency hides under barrier
                xw_pf = g_xw[oidx + (size_t)(t + 1) * Uu];
        }
        __syncthreads();

        // ---- group barrier: release-add our arrival, spin for the 16 CTAs ----
        if (tid == 0) {
            asm volatile("red.release.gpu.global.add.u32 [%0], %1;"
                         :: "l"(ctr), "r"(1u) : "memory");
            unsigned int target = (unsigned int)(16 * (t + 1));
            unsigned int v;
            do {
                asm volatile("ld.global.acquire.gpu.u32 %0, [%1];"
                             : "=r"(v) : "l"(ctr));
            } while (v < target);
        }
        __syncthreads();
    }
}

// ---------------------------------------------------------------------------
// h_final = H[:, T-1, :]
__global__ void copy_hfinal(float* __restrict__ out) {
    int i = blockIdx.x * 256 + threadIdx.x;
    if (i < Bz * Uu) {
        int b = i >> 9, u = i & 511;
        out[(size_t)Bz * Tt * Uu + i] =
            g_xw[((size_t)b * Tt + (Tt - 1)) * Uu + u];
    }
}

// ---------------------------------------------------------------------------
extern "C" void kernel_launch(void* const* d_in, const int* in_sizes, int n_in,
                              void* d_out, int out_size) {
    const float* x   = (const float*)d_in[0];
    const float* w_h = (const float*)d_in[1];
    const float* w_x = (const float*)d_in[2];
    const float* w_y = (const float*)d_in[3];
    const float* b_h = (const float*)d_in[4];
    const float* b_y = (const float*)d_in[5];
    const float* h0  = (const float*)d_in[6];
    float* out = (float*)d_out;

    float* xw = nullptr;
    unsigned int* ctr = nullptr;
    cudaGetSymbolAddress((void**)&xw, g_xw);
    cudaGetSymbolAddress((void**)&ctr, g_ctr);

    dim3 gg(4, 1024);

    // Phase 1: XW = x @ w_x + b_h  (also resets scan counters)
    sgemm_bias<<<gg, 256>>>(x, w_x, b_h, xw, ctr);
    // Phase 2: sequential scan (128 CTAs, 8 groups), H overwrites XW in place
    rnn_scan12<<<128, 256>>>(w_h, h0);
    // Phase 3: Y = H @ w_y + b_y
    sgemm_bias<<<gg, 256>>>(xw, w_y, b_y, out, nullptr);
    // h_final = H[:, T-1, :]
    copy_hfinal<<<64, 256>>>(out);
}